// round 1
// baseline (speedup 1.0000x reference)
#include <cuda_runtime.h>

// Problem constants (static per reference)
#define BATCH 8
#define CIN   32
#define HH    96
#define WW    96
#define OCN   64
#define OHW   96
#define SSZ   (OHW*OHW)      // 9216
#define KK    (CIN*3*3)      // 288
#define TILE_N 128
#define KB     4

// Preprocessed weights: slopes laid out k-major for coalesced chunk loads.
__device__ float d_S0[KK*OCN];
__device__ float d_S1[KK*OCN];
__device__ float d_bias[OCN];

// ---------------------------------------------------------------------------
// Prep: per (oc,k) compute the two interval slopes and the constant term.
// grid(64), block(288)
// ---------------------------------------------------------------------------
__global__ void prep_kernel(const float* __restrict__ pos,
                            const float* __restrict__ val) {
    int oc = blockIdx.x;
    int k  = threadIdx.x;
    __shared__ float red[KK];

    const float* p = pos + ((size_t)(oc*KK + k))*3;
    const float* v = val + ((size_t)(oc*KK + k))*3;
    float p0 = p[0], p1 = p[1], p2 = p[2];
    float v0 = v[0], v1 = v[1], v2 = v[2];
    float dp0 = p1 - p0, dp1 = p2 - p1;
    float s0 = (dp0 > 0.f) ? (v1 - v0) / dp0 : 0.f;
    float s1 = (dp1 > 0.f) ? (v2 - v1) / dp1 : 0.f;

    d_S0[k*OCN + oc] = s0;
    d_S1[k*OCN + oc] = s1;
    red[k] = v0 - s0*p0 - s1*p1;
    __syncthreads();
    if (k == 0) {
        float s = 0.f;
        for (int i = 0; i < KK; i++) s += red[i];
        d_bias[oc] = s;
    }
}

// ---------------------------------------------------------------------------
// Main: implicit GEMM  out[oc,n] = bias[oc] + S0·U0 + S1·U1
//   U0 = clip(x, p0, p1), U1 = clip(x, p1, p2)  built on the fly from the
//   unfolded input (never materialized).
// Block: 128 threads, tile 64 oc x 128 n, thread tile 8x8, KB=4 k-chunks,
// register prefetch of next chunk's gmem loads over current chunk's FMAs.
// grid(SSZ/TILE_N = 72, BATCH)
// ---------------------------------------------------------------------------
__global__ __launch_bounds__(128)
void pw_conv_kernel(const float* __restrict__ x,
                    const float* __restrict__ pos,
                    float* __restrict__ out) {
    const int b     = blockIdx.y;
    const int nbase = blockIdx.x * TILE_N;
    const int tid   = threadIdx.x;
    const int tx    = tid & 15;   // 16 along n
    const int ty    = tid >> 4;   // 8 along oc

    __shared__ float sm_u0[KB][TILE_N];
    __shared__ float sm_u1[KB][TILE_N];
    __shared__ float sm_w0[KB][OCN];
    __shared__ float sm_w1[KB][OCN];

    const float p0 = pos[0], p1 = pos[1], p2 = pos[2];
    const float* xb = x + (size_t)b * (CIN*HH*WW);

    // geometry for this thread's 4 x-loads per chunk (constant across chunks)
    int kk_i[4], oh_i[4], ow_i[4];
#pragma unroll
    for (int i = 0; i < 4; i++) {
        int e = tid + i*128;
        kk_i[i] = e >> 7;
        int nl  = e & 127;
        int s   = nbase + nl;
        oh_i[i] = s / OHW;
        ow_i[i] = s - (s / OHW) * OHW;
    }

    float acc[8][8];
#pragma unroll
    for (int i = 0; i < 8; i++)
#pragma unroll
        for (int j = 0; j < 8; j++) acc[i][j] = 0.f;

    float xr[4];
    float w0r[2], w1r[2];

    // prefetch chunk 0
#pragma unroll
    for (int i = 0; i < 4; i++) {
        int k = kk_i[i];
        int c = k / 9, r = k - c*9;
        int kh = r / 3, kw = r - (r/3)*3;
        int ih = oh_i[i] + kh - 1, iw = ow_i[i] + kw - 1;
        xr[i] = (ih >= 0 && ih < HH && iw >= 0 && iw < WW)
                    ? xb[(c*HH + ih)*WW + iw] : 0.f;
    }
#pragma unroll
    for (int i = 0; i < 2; i++) {
        int e = tid + i*128;
        w0r[i] = d_S0[((e>>6))*OCN + (e & 63)];
        w1r[i] = d_S1[((e>>6))*OCN + (e & 63)];
    }

    for (int k0 = 0; k0 < KK; k0 += KB) {
        // stage current chunk into smem (clamps fused here)
#pragma unroll
        for (int i = 0; i < 4; i++) {
            int e  = tid + i*128;
            int kk = e >> 7, nl = e & 127;
            float xv = xr[i];
            sm_u0[kk][nl] = fminf(fmaxf(xv, p0), p1);
            sm_u1[kk][nl] = fminf(fmaxf(xv, p1), p2);
        }
#pragma unroll
        for (int i = 0; i < 2; i++) {
            int e = tid + i*128;
            sm_w0[e>>6][e & 63] = w0r[i];
            sm_w1[e>>6][e & 63] = w1r[i];
        }
        __syncthreads();

        // prefetch next chunk while we compute on smem
        int kn = k0 + KB;
        if (kn < KK) {
#pragma unroll
            for (int i = 0; i < 4; i++) {
                int k = kn + kk_i[i];
                int c = k / 9, r = k - c*9;
                int kh = r / 3, kw = r - (r/3)*3;
                int ih = oh_i[i] + kh - 1, iw = ow_i[i] + kw - 1;
                xr[i] = (ih >= 0 && ih < HH && iw >= 0 && iw < WW)
                            ? xb[(c*HH + ih)*WW + iw] : 0.f;
            }
#pragma unroll
            for (int i = 0; i < 2; i++) {
                int e = tid + i*128;
                w0r[i] = d_S0[(kn + (e>>6))*OCN + (e & 63)];
                w1r[i] = d_S1[(kn + (e>>6))*OCN + (e & 63)];
            }
        }

        // 8x8 outer-product FMAs on the staged chunk
#pragma unroll
        for (int kk = 0; kk < KB; kk++) {
            float w0v[8], w1v[8], u0v[8], u1v[8];
            *(float4*)&w0v[0] = *(const float4*)&sm_w0[kk][ty*8];
            *(float4*)&w0v[4] = *(const float4*)&sm_w0[kk][ty*8 + 4];
            *(float4*)&w1v[0] = *(const float4*)&sm_w1[kk][ty*8];
            *(float4*)&w1v[4] = *(const float4*)&sm_w1[kk][ty*8 + 4];
            *(float4*)&u0v[0] = *(const float4*)&sm_u0[kk][tx*8];
            *(float4*)&u0v[4] = *(const float4*)&sm_u0[kk][tx*8 + 4];
            *(float4*)&u1v[0] = *(const float4*)&sm_u1[kk][tx*8];
            *(float4*)&u1v[4] = *(const float4*)&sm_u1[kk][tx*8 + 4];
#pragma unroll
            for (int i = 0; i < 8; i++)
#pragma unroll
                for (int j = 0; j < 8; j++)
                    acc[i][j] += w0v[i]*u0v[j] + w1v[i]*u1v[j];
        }
        __syncthreads();
    }

    // epilogue: add bias, vector stores
    const int scol = nbase + tx*8;
#pragma unroll
    for (int i = 0; i < 8; i++) {
        int oc = ty*8 + i;
        float bv = d_bias[oc];
        float* o = out + ((size_t)(b*OCN + oc))*SSZ + scol;
        float4 r0 = make_float4(acc[i][0]+bv, acc[i][1]+bv,
                                acc[i][2]+bv, acc[i][3]+bv);
        float4 r1 = make_float4(acc[i][4]+bv, acc[i][5]+bv,
                                acc[i][6]+bv, acc[i][7]+bv);
        *(float4*)o       = r0;
        *(float4*)(o + 4) = r1;
    }
}

extern "C" void kernel_launch(void* const* d_in, const int* in_sizes, int n_in,
                              void* d_out, int out_size) {
    const float* x   = (const float*)d_in[0];  // [8,32,96,96]
    const float* pos = (const float*)d_in[1];  // [64,32,3,3,3]
    const float* val = (const float*)d_in[2];  // [64,32,3,3,3]
    float* out = (float*)d_out;                // [8,64,96,96]

    prep_kernel<<<OCN, KK>>>(pos, val);
    dim3 grid(SSZ / TILE_N, BATCH);
    pw_conv_kernel<<<grid, 128>>>(x, pos, out);
}

// round 3
// speedup vs baseline: 1.7790x; 1.7790x over previous
#include <cuda_runtime.h>
#include <cstdint>

// ---------------------------------------------------------------------------
// Problem constants (static per reference)
// ---------------------------------------------------------------------------
#define BATCH 8
#define CIN   32
#define HH    96
#define WW    96
#define OCN   64
#define OHW   96
#define SSZ   (OHW*OHW)      // 9216
#define KK    (CIN*3*3)      // 288

// Output tile per block: 8 oh x 16 ow = 128 positions, all 64 oc.
// Block 256 threads: tx(16 ow) x ty(8 oc-octets) x tz(2 oh-halves).
#define TILE_H 8
#define TILE_W 16
#define PATCH_H (TILE_H + 2)   // 10
#define PATCH_W (TILE_W + 2)   // 18
#define PATCH_CH (PATCH_H * PATCH_W)  // 180
#define PATCH_SZ (CIN * PATCH_CH)     // 5760 floats

// Preprocessed slopes, k-major: d_S0[k][oc], d_S1[k][oc]
__device__ float d_S0[KK*OCN];
__device__ float d_S1[KK*OCN];
__device__ float d_bias[OCN];

// ---------------------------------------------------------------------------
// f32x2 packed helpers (FFMA2 path — sm_100+ PTX, not an 'a' feature)
// ---------------------------------------------------------------------------
__device__ __forceinline__ uint64_t pack_dup(float a) {
    uint64_t r;
    asm("mov.b64 %0, {%1, %1};" : "=l"(r) : "f"(a));
    return r;
}
__device__ __forceinline__ void fma2(uint64_t& d, uint64_t a, uint64_t b) {
    asm("fma.rn.f32x2 %0, %1, %2, %0;" : "+l"(d) : "l"(a), "l"(b));
}
__device__ __forceinline__ void unpack2(float& lo, float& hi, uint64_t v) {
    asm("mov.b64 {%0, %1}, %2;" : "=f"(lo), "=f"(hi) : "l"(v));
}

// ---------------------------------------------------------------------------
// Prep: per (oc,k) slopes + constant term.  grid(64), block(288)
// ---------------------------------------------------------------------------
__global__ void prep_w_kernel(const float* __restrict__ pos,
                              const float* __restrict__ val) {
    int oc = blockIdx.x;
    int k  = threadIdx.x;
    __shared__ float red[KK];

    const float* p = pos + ((size_t)(oc*KK + k))*3;
    const float* v = val + ((size_t)(oc*KK + k))*3;
    float p0 = p[0], p1 = p[1], p2 = p[2];
    float v0 = v[0], v1 = v[1], v2 = v[2];
    float dp0 = p1 - p0, dp1 = p2 - p1;
    float s0 = (dp0 > 0.f) ? (v1 - v0) / dp0 : 0.f;
    float s1 = (dp1 > 0.f) ? (v2 - v1) / dp1 : 0.f;

    d_S0[k*OCN + oc] = s0;
    d_S1[k*OCN + oc] = s1;
    red[k] = v0 - s0*p0 - s1*p1;
    __syncthreads();
    if (k == 0) {
        float s = 0.f;
        for (int i = 0; i < KK; i++) s += red[i];
        d_bias[oc] = s;
    }
}

// ---------------------------------------------------------------------------
// Main kernel: patch-resident implicit GEMM with packed f32x2 FMAs.
//   out[oc, p] = bias[oc] + sum_k S0[k,oc]*clip(x,p0,p1) + S1[k,oc]*clip(x,p1,p2)
// Patch (u0,u1 pre-clamped) staged to smem ONCE; main 288-k loop has no
// barriers, no gmem x loads, compile-time LDS offsets.
// ---------------------------------------------------------------------------
__global__ __launch_bounds__(256, 2)
void pw_conv2_kernel(const float* __restrict__ x,
                     const float* __restrict__ pos,
                     float* __restrict__ out) {
    __shared__ float u0p[PATCH_SZ];
    __shared__ float u1p[PATCH_SZ];

    const int tid = threadIdx.x;
    const int tx  = tid & 15;          // ow within tile
    const int ty  = (tid >> 4) & 7;    // oc octet
    const int tz  = tid >> 7;          // oh half (0/1)

    const int b   = blockIdx.z;
    const int oh0 = blockIdx.y * TILE_H;
    const int ow0 = blockIdx.x * TILE_W;

    const float p0 = pos[0], p1 = pos[1], p2 = pos[2];

    // ---- Stage clamped patch: rows [oh0-1, oh0+8], cols [ow0-1, ow0+16] ----
    {
        const float* xb = x + (size_t)b * (CIN*HH*WW);
        for (int idx = tid; idx < PATCH_SZ; idx += 256) {
            int c = idx / PATCH_CH;
            int r = idx - c*PATCH_CH;
            int h = r / PATCH_W;
            int w = r - h*PATCH_W;
            int ih = oh0 - 1 + h;
            int iw = ow0 - 1 + w;
            float xv = 0.f;
            if ((unsigned)ih < HH && (unsigned)iw < WW)
                xv = xb[(c*HH + ih)*WW + iw];
            u0p[idx] = fminf(fmaxf(xv, p0), p1);
            u1p[idx] = fminf(fmaxf(xv, p1), p2);
        }
    }
    __syncthreads();

    // ---- Main loop ----
    // acc[j][pp]: j = oh sub-row (4 per thread), pp = oc pair (8 oc as 4 pairs)
    uint64_t acc[4][4];
#pragma unroll
    for (int j = 0; j < 4; j++)
#pragma unroll
        for (int pp = 0; pp < 4; pp++) acc[j][pp] = 0ull;

    const int rowbase = tz * 4;  // thread's first oh sub-row within the patch
    const float* pu0 = u0p + rowbase * PATCH_W + tx;
    const float* pu1 = u1p + rowbase * PATCH_W + tx;
    const float* pw0 = d_S0 + ty * 8;
    const float* pw1 = d_S1 + ty * 8;

    for (int c = 0; c < CIN; c++) {
#pragma unroll
        for (int kh = 0; kh < 3; kh++) {
#pragma unroll
            for (int kw = 0; kw < 3; kw++) {
                const int koff = (kh*3 + kw) * OCN;
                // weights: 8 oc = 4 packed pairs per array (LDG.128 x2 each)
                ulonglong2 w0a = *(const ulonglong2*)(pw0 + koff);
                ulonglong2 w0b = *(const ulonglong2*)(pw0 + koff + 4);
                ulonglong2 w1a = *(const ulonglong2*)(pw1 + koff);
                ulonglong2 w1b = *(const ulonglong2*)(pw1 + koff + 4);
                // u: 4 oh rows, broadcast-packed
                uint64_t U0[4], U1[4];
#pragma unroll
                for (int j = 0; j < 4; j++) {
                    U0[j] = pack_dup(pu0[(j + kh)*PATCH_W + kw]);
                    U1[j] = pack_dup(pu1[(j + kh)*PATCH_W + kw]);
                }
#pragma unroll
                for (int j = 0; j < 4; j++) {
                    fma2(acc[j][0], U0[j], w0a.x);
                    fma2(acc[j][1], U0[j], w0a.y);
                    fma2(acc[j][2], U0[j], w0b.x);
                    fma2(acc[j][3], U0[j], w0b.y);
                    fma2(acc[j][0], U1[j], w1a.x);
                    fma2(acc[j][1], U1[j], w1a.y);
                    fma2(acc[j][2], U1[j], w1b.x);
                    fma2(acc[j][3], U1[j], w1b.y);
                }
            }
        }
        pu0 += PATCH_CH;
        pu1 += PATCH_CH;
        pw0 += 9 * OCN;
        pw1 += 9 * OCN;
    }

    // ---- Epilogue: unpack, add bias, store ----
    const int ocb = ty * 8;
    float bias[8];
#pragma unroll
    for (int i = 0; i < 8; i++) bias[i] = d_bias[ocb + i];

    float* ob = out + (size_t)b*OCN*SSZ + (size_t)ocb*SSZ
              + (size_t)(oh0 + rowbase)*OHW + (ow0 + tx);
#pragma unroll
    for (int j = 0; j < 4; j++) {
        float* orow = ob + (size_t)j*OHW;
#pragma unroll
        for (int pp = 0; pp < 4; pp++) {
            float lo, hi;
            unpack2(lo, hi, acc[j][pp]);
            orow[(size_t)(2*pp)    *SSZ] = lo + bias[2*pp];
            orow[(size_t)(2*pp + 1)*SSZ] = hi + bias[2*pp + 1];
        }
    }
}

// ---------------------------------------------------------------------------
extern "C" void kernel_launch(void* const* d_in, const int* in_sizes, int n_in,
                              void* d_out, int out_size) {
    const float* x   = (const float*)d_in[0];  // [8,32,96,96]
    const float* pos = (const float*)d_in[1];  // [64,32,3,3,3]
    const float* val = (const float*)d_in[2];  // [64,32,3,3,3]
    float* out = (float*)d_out;                // [8,64,96,96]

    prep_w_kernel<<<OCN, KK>>>(pos, val);
    dim3 grid(OHW / TILE_W, OHW / TILE_H, BATCH);
    pw_conv2_kernel<<<grid, 256>>>(x, pos, out);
}